// round 13
// baseline (speedup 1.0000x reference)
#include <cuda_runtime.h>
#include <cuda_bf16.h>
#include <cuda_fp16.h>
#include <mma.h>
#include <math.h>
#include <stdint.h>

using namespace nvcuda;

#define N_NODES 100000
#define N_EDGES 1600000
#define HID 64
#define SCAN_BLOCKS ((N_NODES + 255) / 256)   // 391

// ---------------- scratch (static device memory; no allocations) ----------------
__device__ int     g_deg[N_NODES];
__device__ float   g_dinv[N_NODES];
__device__ int     g_rowptr[N_NODES + 1];
__device__ int     g_fill[N_NODES];
__device__ int2    g_csr[N_EDGES];               // .x = src, .y = bits of norm weight
__device__ __half2 g_h1h[(size_t)N_NODES * 32];  // GEMM output (gather operand), fp16
__device__ __half2 g_h2h[(size_t)N_NODES * 32];  // agg output (GEMM input), fp16
__device__ int     g_blocksum[SCAN_BLOCKS];
__device__ int     g_blockoff[SCAN_BLOCKS];

// ---------------- preprocessing ----------------
__global__ void k_init_deg() {
    int i = blockIdx.x * blockDim.x + threadIdx.x;
    if (i < N_NODES) g_deg[i] = 1;   // self-loop
}

__global__ void k_hist(const int* __restrict__ ei) {
    int e = blockIdx.x * blockDim.x + threadIdx.x;
    if (e < N_EDGES) {
        int d = ei[N_EDGES + e];
        if ((unsigned)d >= N_NODES) d = 0;
        atomicAdd(&g_deg[d], 1);
    }
}

__global__ void k_blockscan() {
    __shared__ int wsum[8];
    int tid = threadIdx.x;
    int lane = tid & 31;
    int wid = tid >> 5;
    int i = blockIdx.x * 256 + tid;

    int e = 0;
    if (i < N_NODES) {
        int dg = g_deg[i];
        g_dinv[i] = rsqrtf((float)dg);
        e = dg - 1;
    }
    int incl = e;
#pragma unroll
    for (int o = 1; o < 32; o <<= 1) {
        int v = __shfl_up_sync(0xffffffffu, incl, o);
        if (lane >= o) incl += v;
    }
    if (lane == 31) wsum[wid] = incl;
    __syncthreads();
    if (wid == 0) {
        int v = (lane < 8) ? wsum[lane] : 0;
        int s = v;
#pragma unroll
        for (int o = 1; o < 8; o <<= 1) {
            int u = __shfl_up_sync(0xffffffffu, s, o);
            if (lane >= o) s += u;
        }
        if (lane < 8) wsum[lane] = s - v;
    }
    __syncthreads();
    int excl = incl - e + wsum[wid];
    if (i < N_NODES) g_rowptr[i] = excl;
    if (tid == 255) g_blocksum[blockIdx.x] = excl + e;
}

__global__ void k_scanmid() {
    __shared__ int wsum[16];
    int tid = threadIdx.x;
    int lane = tid & 31;
    int wid = tid >> 5;
    int v = (tid < SCAN_BLOCKS) ? g_blocksum[tid] : 0;
    int incl = v;
#pragma unroll
    for (int o = 1; o < 32; o <<= 1) {
        int u = __shfl_up_sync(0xffffffffu, incl, o);
        if (lane >= o) incl += u;
    }
    if (lane == 31) wsum[wid] = incl;
    __syncthreads();
    if (wid == 0) {
        int w = (lane < 16) ? wsum[lane] : 0;
        int s = w;
#pragma unroll
        for (int o = 1; o < 16; o <<= 1) {
            int u = __shfl_up_sync(0xffffffffu, s, o);
            if (lane >= o) s += u;
        }
        if (lane < 16) wsum[lane] = s - w;
    }
    __syncthreads();
    int excl = incl - v + wsum[wid];
    if (tid < SCAN_BLOCKS) g_blockoff[tid] = excl;
    if (tid == SCAN_BLOCKS - 1) g_rowptr[N_NODES] = excl + v;
}

__global__ void k_addoff() {
    int i = blockIdx.x * blockDim.x + threadIdx.x;
    if (i < N_NODES) {
        int v = g_rowptr[i] + g_blockoff[i >> 8];
        g_rowptr[i] = v;
        g_fill[i] = v;
    }
}

__global__ void k_scatter(const int* __restrict__ ei) {
    int e = blockIdx.x * blockDim.x + threadIdx.x;
    if (e < N_EDGES) {
        int s = ei[e];
        int d = ei[N_EDGES + e];
        if ((unsigned)s >= N_NODES) s = 0;
        if ((unsigned)d >= N_NODES) d = 0;
        int pos = atomicAdd(&g_fill[d], 1);
        if ((unsigned)pos < N_EDGES) {
            float w = g_dinv[s] * g_dinv[d];
            g_csr[pos] = make_int2(s, __float_as_int(w));
        }
    }
}

// ---------------- HMMA GEMM: g_h1h[N,64](fp16) = X[N,KDIM] @ W[KDIM,64] ------
// 256 threads (8 warps), tile M=128 x N=64, K chunked by 64; software-pipelined:
// chunk c+1's A/B global loads are prefetched into registers BEFORE chunk c's
// MMA, so DRAM latency overlaps tensor work (fp32->fp16 convert deferred to
// the store phase). Warp w owns rows [w*16,w*16+16) as 1x4 wmma fragments.
// SRC=0: X = fp32 param (layer 1).  SRC=1: X = g_h2h fp16 (layers 2,3; 1 chunk,
// prefetch branch compiles out).
template <int KDIM, int SRC>
__global__ void __launch_bounds__(256, 2)
k_gemm_mma(const float* __restrict__ Xp, const float* __restrict__ Wp) {
    constexpr int LDA = 72;   // halves per As/Bs row (144B, 16B-aligned)
    constexpr int LDC = 68;   // floats per Cs row (272B)
    __shared__ __align__(16) char sbuf[128 * LDC * 4];   // 34816 B
    __half* As = (__half*)sbuf;                          // 128*72*2 = 18432
    __half* Bs = (__half*)(sbuf + 128 * LDA * 2);        // 64*72*2  =  9216
    float*  Cs = (float*)sbuf;

    int tid = threadIdx.x;
    int wid = tid >> 5;
    int base = blockIdx.x * 128;
    int m0 = wid * 16;

    wmma::fragment<wmma::accumulator, 16, 16, 16, float> acc[4];
#pragma unroll
    for (int j = 0; j < 4; j++) wmma::fill_fragment(acc[j], 0.f);

    constexpr int NCHUNK = KDIM / 64;

    // prefetch registers
    float4 pa[8];      // SRC==0: 4 positions x 2 float4
    uint4  qa[4];      // SRC==1: 4 positions x 1 uint4
    float4 pb[4];      // B: 2 positions x 2 float4

    // ---- prefetch chunk 0 ----
    if (SRC == 0) {
#pragma unroll
        for (int it = 0; it < 4; it++) {
            int idx = tid + 256 * it;
            int r = idx >> 3, k8 = idx & 7;
            int grow = base + r;
            pa[2 * it]     = make_float4(0.f, 0.f, 0.f, 0.f);
            pa[2 * it + 1] = make_float4(0.f, 0.f, 0.f, 0.f);
            if (grow < N_NODES) {
                const float* xr = &Xp[(size_t)grow * KDIM + k8 * 8];
                pa[2 * it]     = *(const float4*)xr;
                pa[2 * it + 1] = *(const float4*)(xr + 4);
            }
        }
    } else {
        const uint4* X = (const uint4*)g_h2h;
#pragma unroll
        for (int it = 0; it < 4; it++) {
            int idx = tid + 256 * it;
            int r = idx >> 3, k8 = idx & 7;
            int grow = base + r;
            qa[it] = make_uint4(0u, 0u, 0u, 0u);
            if (grow < N_NODES) qa[it] = X[(size_t)grow * 8 + k8];
        }
    }
#pragma unroll
    for (int it = 0; it < 2; it++) {
        int idx = tid + 256 * it;
        int k = idx >> 3, n8 = idx & 7;
        const float* wr = &Wp[(size_t)k * 64 + n8 * 8];
        pb[2 * it]     = *(const float4*)wr;
        pb[2 * it + 1] = *(const float4*)(wr + 4);
    }

    for (int c = 0; c < NCHUNK; c++) {
        __syncthreads();   // previous chunk's MMA done; smem writable
        // ---- store staged chunk (convert here) ----
        if (SRC == 0) {
#pragma unroll
            for (int it = 0; it < 4; it++) {
                int idx = tid + 256 * it;
                int r = idx >> 3, k8 = idx & 7;
                __half2 h[4];
                h[0] = __floats2half2_rn(pa[2 * it].x, pa[2 * it].y);
                h[1] = __floats2half2_rn(pa[2 * it].z, pa[2 * it].w);
                h[2] = __floats2half2_rn(pa[2 * it + 1].x, pa[2 * it + 1].y);
                h[3] = __floats2half2_rn(pa[2 * it + 1].z, pa[2 * it + 1].w);
                *(uint4*)&As[r * LDA + k8 * 8] = *(uint4*)h;
            }
        } else {
#pragma unroll
            for (int it = 0; it < 4; it++) {
                int idx = tid + 256 * it;
                int r = idx >> 3, k8 = idx & 7;
                *(uint4*)&As[r * LDA + k8 * 8] = qa[it];
            }
        }
#pragma unroll
        for (int it = 0; it < 2; it++) {
            int idx = tid + 256 * it;
            int k = idx >> 3, n8 = idx & 7;
            __half2 h[4];
            h[0] = __floats2half2_rn(pb[2 * it].x, pb[2 * it].y);
            h[1] = __floats2half2_rn(pb[2 * it].z, pb[2 * it].w);
            h[2] = __floats2half2_rn(pb[2 * it + 1].x, pb[2 * it + 1].y);
            h[3] = __floats2half2_rn(pb[2 * it + 1].z, pb[2 * it + 1].w);
            *(uint4*)&Bs[k * LDA + n8 * 8] = *(uint4*)h;
        }
        // ---- prefetch chunk c+1 (LDGs in flight during barrier + MMA) ----
        if (SRC == 0 && c + 1 < NCHUNK) {
#pragma unroll
            for (int it = 0; it < 4; it++) {
                int idx = tid + 256 * it;
                int r = idx >> 3, k8 = idx & 7;
                int grow = base + r;
                pa[2 * it]     = make_float4(0.f, 0.f, 0.f, 0.f);
                pa[2 * it + 1] = make_float4(0.f, 0.f, 0.f, 0.f);
                if (grow < N_NODES) {
                    const float* xr =
                        &Xp[(size_t)grow * KDIM + (c + 1) * 64 + k8 * 8];
                    pa[2 * it]     = *(const float4*)xr;
                    pa[2 * it + 1] = *(const float4*)(xr + 4);
                }
            }
#pragma unroll
            for (int it = 0; it < 2; it++) {
                int idx = tid + 256 * it;
                int k = idx >> 3, n8 = idx & 7;
                const float* wr = &Wp[(size_t)((c + 1) * 64 + k) * 64 + n8 * 8];
                pb[2 * it]     = *(const float4*)wr;
                pb[2 * it + 1] = *(const float4*)(wr + 4);
            }
        }
        __syncthreads();

        // ---- 4 k-steps of 16 ----
#pragma unroll
        for (int kk = 0; kk < 4; kk++) {
            wmma::fragment<wmma::matrix_a, 16, 16, 16, __half, wmma::row_major> a;
            wmma::load_matrix_sync(a, &As[m0 * LDA + kk * 16], LDA);
#pragma unroll
            for (int j = 0; j < 4; j++) {
                wmma::fragment<wmma::matrix_b, 16, 16, 16, __half, wmma::row_major> b;
                wmma::load_matrix_sync(b, &Bs[kk * 16 * LDA + j * 16], LDA);
                wmma::mma_sync(acc[j], a, b, acc[j]);
            }
        }
    }

    // ---- epilogue: fragments -> Cs (fp32) -> g_h1h (fp16) ----
    __syncthreads();   // all warps done reading As/Bs (Cs aliases them)
#pragma unroll
    for (int j = 0; j < 4; j++)
        wmma::store_matrix_sync(&Cs[m0 * LDC + j * 16], acc[j], LDC,
                                wmma::mem_row_major);
    __syncthreads();

    // 256 threads, 128 rows: thread t -> row t>>1, half (t&1)
    {
        int r = tid >> 1;
        int half = tid & 1;
        int row = base + r;
        if (row < N_NODES) {
            const float* cr = &Cs[r * LDC + half * 32];
            __half2 h[16];
#pragma unroll
            for (int p = 0; p < 16; p++) {
                float2 f = *(const float2*)&cr[2 * p];
                h[p] = __floats2half2_rn(f.x, f.y);
            }
            uint4* o = (uint4*)&g_h1h[(size_t)row * 32 + half * 16];
#pragma unroll
            for (int q = 0; q < 4; q++) o[q] = ((uint4*)h)[q];
        }
    }
}

// ---------------- Aggregation + epilogue: warp per node ----------------
// OUT[i] = sum_{e: dst=i} w_e * h1h[src_e] + dinv[i]^2 * h1h[i] + bias
// MODE=1: relu + L2-normalize -> g_h2h (fp16).  MODE=0: plain -> OUTp (fp32).
template <int MODE>
__global__ void k_agg(const float* __restrict__ bias, float* __restrict__ OUTp) {
    int gwarp = (blockIdx.x * blockDim.x + threadIdx.x) >> 5;
    int lane = threadIdx.x & 31;
    if (gwarp >= N_NODES) return;
    int i = gwarp;

    float di = g_dinv[i];
    int beg = g_rowptr[i];
    int end = g_rowptr[i + 1];

    const __half2* __restrict__ H = g_h1h;
    float2 hv = __half22float2(H[(size_t)i * 32 + lane]);
    float wself = di * di;
    float a0 = wself * hv.x;
    float a1 = wself * hv.y;

    int j = beg;
    // 8-wide unrolled edge loop for deep gather MLP
    for (; j + 8 <= end; j += 8) {
        int2 e[8];
        float2 h[8];
#pragma unroll
        for (int q = 0; q < 8; q++) e[q] = g_csr[j + q];
#pragma unroll
        for (int q = 0; q < 8; q++)
            h[q] = __half22float2(H[(size_t)e[q].x * 32 + lane]);
#pragma unroll
        for (int q = 0; q < 8; q++) {
            float w = __int_as_float(e[q].y);
            a0 += w * h[q].x;
            a1 += w * h[q].y;
        }
    }
    for (; j < end; j++) {
        int2 sw = g_csr[j];
        float w = __int_as_float(sw.y);
        float2 hs = __half22float2(H[(size_t)sw.x * 32 + lane]);
        a0 += w * hs.x;
        a1 += w * hs.y;
    }

    float2 b = ((const float2*)bias)[lane];
    a0 += b.x;
    a1 += b.y;

    if (MODE == 1) {
        a0 = fmaxf(a0, 0.f);
        a1 = fmaxf(a1, 0.f);
        float ss = a0 * a0 + a1 * a1;
#pragma unroll
        for (int o = 16; o; o >>= 1) ss += __shfl_xor_sync(0xffffffffu, ss, o);
        float inv = 1.f / fmaxf(sqrtf(ss), 1e-12f);
        a0 *= inv;
        a1 *= inv;
        g_h2h[(size_t)i * 32 + lane] = __floats2half2_rn(a0, a1);
    } else {
        ((float2*)OUTp)[(size_t)i * 32 + lane] = make_float2(a0, a1);
    }
}

// ---------------- launch ----------------
extern "C" void kernel_launch(void* const* d_in, const int* in_sizes, int n_in,
                              void* d_out, int out_size) {
    const float* x = (const float*)d_in[0];
    const int* ei = (const int*)d_in[1];     // int32 edge_index [2, E]
    const float* W1 = (const float*)d_in[2];
    const float* b1 = (const float*)d_in[3];
    const float* W2 = (const float*)d_in[4];
    const float* b2 = (const float*)d_in[5];
    const float* W3 = (const float*)d_in[6];
    const float* b3 = (const float*)d_in[7];
    float* out = (float*)d_out;

    const int T = 256;
    int gemm_grid = (N_NODES + 127) / 128;
    int agg_grid = (N_NODES * 32 + T - 1) / T;

    // preprocessing with gemm1 at launch index 3 (ncu capture target)
    k_init_deg<<<SCAN_BLOCKS, T>>>();                       // 0
    k_hist<<<(N_EDGES + T - 1) / T, T>>>(ei);               // 1
    k_blockscan<<<SCAN_BLOCKS, T>>>();                      // 2
    k_gemm_mma<256, 0><<<gemm_grid, 256>>>(x, W1);          // 3  <- profiled
    k_scanmid<<<1, 512>>>();                                // 4
    k_addoff<<<SCAN_BLOCKS, T>>>();                         // 5
    k_scatter<<<(N_EDGES + T - 1) / T, T>>>(ei);            // 6

    // layer 1 aggregation
    k_agg<1><<<agg_grid, T>>>(b1, nullptr);                 // 7
    // layer 2
    k_gemm_mma<64, 1><<<gemm_grid, 256>>>(nullptr, W2);     // 8
    k_agg<1><<<agg_grid, T>>>(b2, nullptr);                 // 9
    // layer 3
    k_gemm_mma<64, 1><<<gemm_grid, 256>>>(nullptr, W3);     // 10
    k_agg<0><<<agg_grid, T>>>(b3, out);                     // 11
}